// round 7
// baseline (speedup 1.0000x reference)
#include <cuda_runtime.h>
#include <cuda_bf16.h>
#include <math.h>
#include <stdint.h>

#define H_DIM 4096
#define E_DIM 64
#define TOPK  8
#define BM 128                    // tokens per CTA
#define BK 16                     // k per chunk
#define NCHUNK (H_DIM / BK)       // 256
#define THREADS 256

#define A_STRIDE 132              // floats per As row (16B aligned, bank-safe)
#define B_STRIDE 68               // floats per Bs row

typedef unsigned long long u64;

__device__ __forceinline__ void fma2(u64& d, u64 a, u64 b) {
    asm("fma.rn.f32x2 %0, %1, %2, %0;" : "+l"(d) : "l"(a), "l"(b));
}
__device__ __forceinline__ u64 pk2(float x) {   // (x, x)
    u64 r;
    asm("mov.b64 %0, {%1, %1};" : "=l"(r) : "f"(x));
    return r;
}
__device__ __forceinline__ void upk(u64 v, float& lo, float& hi) {
    asm("mov.b64 {%0, %1}, %2;" : "=f"(lo), "=f"(hi) : "l"(v));
}

// ---------------------------------------------------------------------------
// Kernel 1: router logits GEMM.  C[T,64] = A[T,4096] @ W[64,4096]^T
// 128-token CTA tile, 256 threads, 4 tokens x 8 experts per thread.
// Per-output accumulation: strict serial k=0..4095, RN fp32 fma ->
// bit-identical to the verified R1 kernel.
// ---------------------------------------------------------------------------
__global__ __launch_bounds__(256) void router_gemm_kernel(
    const float* __restrict__ A, const float* __restrict__ W,
    float* __restrict__ logits)
{
    __shared__ float As[2][BK][A_STRIDE];   // k-major: As[s][k][token]
    __shared__ float Bs[2][BK][B_STRIDE];   // k-major: Bs[s][k][expert]

    const int tid = threadIdx.x;
    const int tx  = tid & 7;        // expert group: experts tx*8 .. tx*8+7
    const int ty  = tid >> 3;       // token group:  tokens  ty*4 .. ty*4+3
    const int m0  = blockIdx.x * BM;

    // loader mapping
    const int a_tok = tid >> 2;             // 0..63 (i adds +64)
    const int a_c4  = (tid & 3) << 2;       // 0,4,8,12
    const int b_e   = tid >> 2;             // 0..63
    const int b_c4  = (tid & 3) << 2;

    const float* aptr0 = A + (size_t)(m0 + a_tok) * H_DIM + a_c4;
    const float* aptr1 = A + (size_t)(m0 + a_tok + 64) * H_DIM + a_c4;
    const float* bptr  = W + (size_t)b_e * H_DIM + b_c4;

    u64 acc[4][4];
    #pragma unroll
    for (int t = 0; t < 4; t++)
        #pragma unroll
        for (int p = 0; p < 4; p++) acc[t][p] = 0ull;

    float4 pa0 = *reinterpret_cast<const float4*>(aptr0);
    float4 pa1 = *reinterpret_cast<const float4*>(aptr1);
    float4 pb  = *reinterpret_cast<const float4*>(bptr);

    for (int chunk = 0; chunk < NCHUNK; ++chunk) {
        const int s = chunk & 1;

        // store this chunk's staged registers
        {
            float a0[4] = {pa0.x, pa0.y, pa0.z, pa0.w};
            float a1[4] = {pa1.x, pa1.y, pa1.z, pa1.w};
            float bb[4] = {pb.x,  pb.y,  pb.z,  pb.w};
            #pragma unroll
            for (int j = 0; j < 4; j++) {
                As[s][a_c4 + j][a_tok]      = a0[j];
                As[s][a_c4 + j][a_tok + 64] = a1[j];
                Bs[s][b_c4 + j][b_e]        = bb[j];
            }
        }
        // prefetch next chunk (global) while this chunk computes
        if (chunk + 1 < NCHUNK) {
            const int k0 = (chunk + 1) * BK;
            pa0 = *reinterpret_cast<const float4*>(aptr0 + k0);
            pa1 = *reinterpret_cast<const float4*>(aptr1 + k0);
            pb  = *reinterpret_cast<const float4*>(bptr  + k0);
        }
        __syncthreads();

        // operand-prefetched inner loop over k
        float4 a = *reinterpret_cast<const float4*>(&As[s][0][ty << 2]);
        ulonglong2 bA = *reinterpret_cast<const ulonglong2*>(&Bs[s][0][tx << 3]);
        ulonglong2 bB = *reinterpret_cast<const ulonglong2*>(&Bs[s][0][(tx << 3) + 4]);

        #pragma unroll
        for (int k = 0; k < BK; k++) {
            float4 an; ulonglong2 bAn, bBn;
            if (k + 1 < BK) {
                an  = *reinterpret_cast<const float4*>(&As[s][k + 1][ty << 2]);
                bAn = *reinterpret_cast<const ulonglong2*>(&Bs[s][k + 1][tx << 3]);
                bBn = *reinterpret_cast<const ulonglong2*>(&Bs[s][k + 1][(tx << 3) + 4]);
            }
            u64 t0 = pk2(a.x), t1 = pk2(a.y), t2 = pk2(a.z), t3 = pk2(a.w);
            fma2(acc[0][0], t0, bA.x); fma2(acc[0][1], t0, bA.y);
            fma2(acc[0][2], t0, bB.x); fma2(acc[0][3], t0, bB.y);
            fma2(acc[1][0], t1, bA.x); fma2(acc[1][1], t1, bA.y);
            fma2(acc[1][2], t1, bB.x); fma2(acc[1][3], t1, bB.y);
            fma2(acc[2][0], t2, bA.x); fma2(acc[2][1], t2, bA.y);
            fma2(acc[2][2], t2, bB.x); fma2(acc[2][3], t2, bB.y);
            fma2(acc[3][0], t3, bA.x); fma2(acc[3][1], t3, bA.y);
            fma2(acc[3][2], t3, bB.x); fma2(acc[3][3], t3, bB.y);
            a = an; bA = bAn; bB = bBn;
        }
        __syncthreads();
    }

    // epilogue: tokens m0+ty*4+t, experts tx*8..tx*8+7
    #pragma unroll
    for (int t = 0; t < 4; t++) {
        const int m = m0 + (ty << 2) + t;
        float4 o0, o1;
        upk(acc[t][0], o0.x, o0.y); upk(acc[t][1], o0.z, o0.w);
        upk(acc[t][2], o1.x, o1.y); upk(acc[t][3], o1.z, o1.w);
        float* dst = logits + (size_t)m * E_DIM + (tx << 3);
        *reinterpret_cast<float4*>(dst)     = o0;
        *reinterpret_cast<float4*>(dst + 4) = o1;
    }
}

// ---------------------------------------------------------------------------
// Kernel 2: top-8 + renormalized softmax scores (unchanged, verified)
// ---------------------------------------------------------------------------
__global__ __launch_bounds__(256) void topk_kernel(
    const float* __restrict__ logits,
    float* __restrict__ scores,
    float* __restrict__ indices, int T)
{
    const int warp = (int)((blockIdx.x * blockDim.x + threadIdx.x) >> 5);
    const int lane = threadIdx.x & 31;
    if (warp >= T) return;

    const float* lg = logits + (size_t)warp * E_DIM;
    float v0 = lg[lane];
    float v1 = lg[lane + 32];

    float topv[TOPK];
    int   topi[TOPK];

    #pragma unroll
    for (int r = 0; r < TOPK; r++) {
        bool p   = (v0 >= v1);           // tie -> lower index
        float lv = p ? v0 : v1;
        int   li = p ? lane : lane + 32;
        #pragma unroll
        for (int off = 16; off > 0; off >>= 1) {
            float ov = __shfl_xor_sync(0xffffffffu, lv, off);
            int   oi = __shfl_xor_sync(0xffffffffu, li, off);
            if (ov > lv || (ov == lv && oi < li)) { lv = ov; li = oi; }
        }
        topv[r] = lv; topi[r] = li;
        if (li == lane)           v0 = -INFINITY;
        else if (li == lane + 32) v1 = -INFINITY;
    }

    if (lane == 0) {
        const float m = topv[0];
        float e[TOPK], s = 0.f;
        #pragma unroll
        for (int r = 0; r < TOPK; r++) { e[r] = expf(topv[r] - m); s += e[r]; }
        const float inv = 1.f / s;
        #pragma unroll
        for (int r = 0; r < TOPK; r++) {
            scores [(size_t)warp * TOPK + r] = e[r] * inv;
            indices[(size_t)warp * TOPK + r] = (float)topi[r];
        }
    }
}

// ---------------------------------------------------------------------------
extern "C" void kernel_launch(void* const* d_in, const int* in_sizes, int n_in,
                              void* d_out, int out_size)
{
    const float* hs = (const float*)d_in[0];   // hidden_states [T, 4096]
    const float* w  = (const float*)d_in[1];   // weight        [64, 4096]
    const int T = in_sizes[0] / H_DIM;

    float* out     = (float*)d_out;
    float* logits  = out;                                  // T*64
    float* scores  = out + (size_t)T * E_DIM;              // T*8
    float* indices = scores + (size_t)T * TOPK;            // T*8 (as floats)

    router_gemm_kernel<<<T / BM, 256>>>(hs, w, logits);

    const int warps_per_block = 256 / 32;
    const int grid = (T + warps_per_block - 1) / warps_per_block;
    topk_kernel<<<grid, 256>>>(logits, scores, indices, T);
}

// round 8
// speedup vs baseline: 1.4523x; 1.4523x over previous
#include <cuda_runtime.h>
#include <cuda_bf16.h>
#include <math.h>
#include <stdint.h>

#define H_DIM 4096
#define E_DIM 64
#define TOPK  8
#define BM    128                 // tokens per CTA
#define KC    64                  // K elements per chunk (= one accumulation segment)
#define NCHUNK (H_DIM / KC)       // 64
#define THREADS 256

#define A_PL  (BM * KC * 2)       // 16384 B per A bf16 plane
#define B_PL  (E_DIM * KC * 2)    // 8192  B per B bf16 plane
#define STAGE_SZ (3 * A_PL + 3 * B_PL)   // 73728 B
#define TILE_SZ (2 * STAGE_SZ)           // 147456 B
#define DYN_SZ (TILE_SZ + 256)

__device__ __forceinline__ uint32_t s2u(const void* p) {
    uint32_t a;
    asm("{ .reg .u64 t; cvta.to.shared.u64 t, %1; cvt.u32.u64 %0, t; }" : "=r"(a) : "l"(p));
    return a;
}
__device__ __forceinline__ uint32_t swz(uint32_t b) { return b ^ ((b >> 3) & 0x70); }

// 3-way bf16 split of one float4: v = h + m + l  (verified R5)
__device__ __forceinline__ void cvt_store3(float4 v, uint32_t hB, uint32_t mB, uint32_t lB,
                                           int row, int c4) {
    uint32_t h01, h23, m01, m23, l01, l23;
    asm("cvt.rn.bf16x2.f32 %0, %1, %2;" : "=r"(h01) : "f"(v.y), "f"(v.x));
    asm("cvt.rn.bf16x2.f32 %0, %1, %2;" : "=r"(h23) : "f"(v.w), "f"(v.z));
    float h0 = __uint_as_float(h01 << 16);
    float h1 = __uint_as_float(h01 & 0xFFFF0000u);
    float h2 = __uint_as_float(h23 << 16);
    float h3 = __uint_as_float(h23 & 0xFFFF0000u);
    float r0 = v.x - h0, r1 = v.y - h1, r2 = v.z - h2, r3 = v.w - h3;
    asm("cvt.rn.bf16x2.f32 %0, %1, %2;" : "=r"(m01) : "f"(r1), "f"(r0));
    asm("cvt.rn.bf16x2.f32 %0, %1, %2;" : "=r"(m23) : "f"(r3), "f"(r2));
    float q0 = __uint_as_float(m01 << 16);
    float q1 = __uint_as_float(m01 & 0xFFFF0000u);
    float q2 = __uint_as_float(m23 << 16);
    float q3 = __uint_as_float(m23 & 0xFFFF0000u);
    asm("cvt.rn.bf16x2.f32 %0, %1, %2;" : "=r"(l01) : "f"(r1 - q1), "f"(r0 - q0));
    asm("cvt.rn.bf16x2.f32 %0, %1, %2;" : "=r"(l23) : "f"(r3 - q3), "f"(r2 - q2));
    uint32_t off = swz((uint32_t)(row * 128 + c4 * 8));
    asm volatile("st.shared.v2.b32 [%0], {%1,%2};" :: "r"(hB + off), "r"(h01), "r"(h23));
    asm volatile("st.shared.v2.b32 [%0], {%1,%2};" :: "r"(mB + off), "r"(m01), "r"(m23));
    asm volatile("st.shared.v2.b32 [%0], {%1,%2};" :: "r"(lB + off), "r"(l01), "r"(l23));
}

__device__ __forceinline__ void load_chunk(const float* __restrict__ A,
                                           const float* __restrict__ W,
                                           int m0, int chunk, int tid,
                                           float4* ra, float4* rb) {
    const int k0 = chunk * KC;
    #pragma unroll
    for (int i = 0; i < 8; i++) {
        int idx = tid + i * THREADS;
        int row = idx >> 4;
        int c4  = idx & 15;
        ra[i] = *reinterpret_cast<const float4*>(A + (size_t)(m0 + row) * H_DIM + k0 + c4 * 4);
    }
    #pragma unroll
    for (int i = 0; i < 4; i++) {
        int idx = tid + i * THREADS;
        int row = idx >> 4;
        int c4  = idx & 15;
        rb[i] = *reinterpret_cast<const float4*>(W + (size_t)row * H_DIM + k0 + c4 * 4);
    }
}

__device__ __forceinline__ void ldsm4(uint32_t addr, uint32_t& r0, uint32_t& r1,
                                      uint32_t& r2, uint32_t& r3) {
    asm volatile("ldmatrix.sync.aligned.m8n8.x4.shared.b16 {%0,%1,%2,%3}, [%4];"
                 : "=r"(r0), "=r"(r1), "=r"(r2), "=r"(r3) : "r"(addr));
}

__device__ __forceinline__ void mma16816(float* d, const uint32_t* a, const uint32_t* b) {
    asm volatile(
        "mma.sync.aligned.m16n8k16.row.col.f32.bf16.bf16.f32 "
        "{%0,%1,%2,%3}, {%4,%5,%6,%7}, {%8,%9}, {%0,%1,%2,%3};"
        : "+f"(d[0]), "+f"(d[1]), "+f"(d[2]), "+f"(d[3])
        : "r"(a[0]), "r"(a[1]), "r"(a[2]), "r"(a[3]), "r"(b[0]), "r"(b[1]));
}

// ---------------------------------------------------------------------------
// HMMA bf16 3-way-split GEMM, SEGMENTED accumulation:
// per 64-k chunk the 24 chained mmas go into a fresh fragment (bias ~ 24 ulp
// of the segment), then fold into master fp32 accumulators with RN adds.
// ---------------------------------------------------------------------------
__global__ __launch_bounds__(THREADS, 1) void router_gemm_tc(
    const float* __restrict__ A, const float* __restrict__ W,
    float* __restrict__ logits)
{
    extern __shared__ char dsm[];
    const uint32_t base = (s2u(dsm) + 127u) & ~127u;
    uint32_t stage_base[2] = { base, base + STAGE_SZ };

    const int tid  = threadIdx.x;
    const int warp = tid >> 5;
    const int lane = tid & 31;
    const int m0   = blockIdx.x * BM;

    const int a_row   = warp * 16 + (lane & 15);
    const int a_khalf = lane >> 4;
    const uint32_t a_off0 = (uint32_t)(a_row * 128 + a_khalf * 16);
    const int b_rowl  = ((lane >> 4) << 3) + (lane & 7);
    const int b_khalf = (lane >> 3) & 1;
    const uint32_t b_off0 = (uint32_t)(b_rowl * 128 + b_khalf * 16);

    float accM[8][4];     // master fp32 accumulators
    #pragma unroll
    for (int nt = 0; nt < 8; nt++)
        #pragma unroll
        for (int j = 0; j < 4; j++) accM[nt][j] = 0.f;

    float4 na[8], nb[4];
    load_chunk(A, W, m0, 0, tid, na, nb);

    for (int chunk = 0; chunk < NCHUNK; ++chunk) {
        const int s = chunk & 1;
        float4 ca[8], cb[4];
        #pragma unroll
        for (int i = 0; i < 8; i++) ca[i] = na[i];
        #pragma unroll
        for (int i = 0; i < 4; i++) cb[i] = nb[i];
        if (chunk + 1 < NCHUNK) load_chunk(A, W, m0, chunk + 1, tid, na, nb);

        const uint32_t aH = stage_base[s];
        const uint32_t aM = aH + A_PL;
        const uint32_t aL = aM + A_PL;
        const uint32_t bH = aL + A_PL;
        const uint32_t bMp = bH + B_PL;
        const uint32_t bLp = bMp + B_PL;

        #pragma unroll
        for (int i = 0; i < 8; i++) {
            int idx = tid + i * THREADS;
            cvt_store3(ca[i], aH, aM, aL, idx >> 4, idx & 15);
        }
        #pragma unroll
        for (int i = 0; i < 4; i++) {
            int idx = tid + i * THREADS;
            cvt_store3(cb[i], bH, bMp, bLp, idx >> 4, idx & 15);
        }
        __syncthreads();

        // fresh segment accumulators
        float accS[8][4];
        #pragma unroll
        for (int nt = 0; nt < 8; nt++)
            #pragma unroll
            for (int j = 0; j < 4; j++) accS[nt][j] = 0.f;

        #pragma unroll
        for (int ks = 0; ks < 4; ks++) {
            const uint32_t ka = (uint32_t)(ks * 32);
            uint32_t ah[4], am[4], al[4];
            ldsm4(aH + swz(a_off0 + ka), ah[0], ah[1], ah[2], ah[3]);
            ldsm4(aM + swz(a_off0 + ka), am[0], am[1], am[2], am[3]);
            ldsm4(aL + swz(a_off0 + ka), al[0], al[1], al[2], al[3]);

            uint32_t bh[8][2], bm[8][2], bl[8][2];
            #pragma unroll
            for (int p = 0; p < 4; p++) {
                const uint32_t boff = swz(b_off0 + (uint32_t)(p * 16 * 128) + ka);
                ldsm4(bH  + boff, bh[2*p][0], bh[2*p][1], bh[2*p+1][0], bh[2*p+1][1]);
                ldsm4(bMp + boff, bm[2*p][0], bm[2*p][1], bm[2*p+1][0], bm[2*p+1][1]);
                ldsm4(bLp + boff, bl[2*p][0], bl[2*p][1], bl[2*p+1][0], bl[2*p+1][1]);
            }

            #pragma unroll
            for (int nt = 0; nt < 8; nt++) mma16816(accS[nt], ah, bh[nt]);  // hh
            #pragma unroll
            for (int nt = 0; nt < 8; nt++) mma16816(accS[nt], ah, bm[nt]);  // hm
            #pragma unroll
            for (int nt = 0; nt < 8; nt++) mma16816(accS[nt], am, bh[nt]);  // mh
            #pragma unroll
            for (int nt = 0; nt < 8; nt++) mma16816(accS[nt], ah, bl[nt]);  // hl
            #pragma unroll
            for (int nt = 0; nt < 8; nt++) mma16816(accS[nt], al, bh[nt]);  // lh
            #pragma unroll
            for (int nt = 0; nt < 8; nt++) mma16816(accS[nt], am, bm[nt]);  // mm
        }

        // fold segment into master with RN fp32 adds
        #pragma unroll
        for (int nt = 0; nt < 8; nt++)
            #pragma unroll
            for (int j = 0; j < 4; j++) accM[nt][j] += accS[nt][j];
    }

    const int r0  = m0 + warp * 16 + (lane >> 2);
    const int col = (lane & 3) * 2;
    #pragma unroll
    for (int nt = 0; nt < 8; nt++) {
        float* d0 = logits + (size_t)r0 * E_DIM + nt * 8 + col;
        float* d1 = logits + (size_t)(r0 + 8) * E_DIM + nt * 8 + col;
        *reinterpret_cast<float2*>(d0) = make_float2(accM[nt][0], accM[nt][1]);
        *reinterpret_cast<float2*>(d1) = make_float2(accM[nt][2], accM[nt][3]);
    }
}

// ---------------------------------------------------------------------------
// Kernel 2: top-8 + renormalized softmax scores (unchanged, verified)
// ---------------------------------------------------------------------------
__global__ __launch_bounds__(256) void topk_kernel(
    const float* __restrict__ logits,
    float* __restrict__ scores,
    float* __restrict__ indices, int T)
{
    const int warp = (int)((blockIdx.x * blockDim.x + threadIdx.x) >> 5);
    const int lane = threadIdx.x & 31;
    if (warp >= T) return;

    const float* lg = logits + (size_t)warp * E_DIM;
    float v0 = lg[lane];
    float v1 = lg[lane + 32];

    float topv[TOPK];
    int   topi[TOPK];

    #pragma unroll
    for (int r = 0; r < TOPK; r++) {
        bool p   = (v0 >= v1);
        float lv = p ? v0 : v1;
        int   li = p ? lane : lane + 32;
        #pragma unroll
        for (int off = 16; off > 0; off >>= 1) {
            float ov = __shfl_xor_sync(0xffffffffu, lv, off);
            int   oi = __shfl_xor_sync(0xffffffffu, li, off);
            if (ov > lv || (ov == lv && oi < li)) { lv = ov; li = oi; }
        }
        topv[r] = lv; topi[r] = li;
        if (li == lane)           v0 = -INFINITY;
        else if (li == lane + 32) v1 = -INFINITY;
    }

    if (lane == 0) {
        const float m = topv[0];
        float e[TOPK], s = 0.f;
        #pragma unroll
        for (int r = 0; r < TOPK; r++) { e[r] = expf(topv[r] - m); s += e[r]; }
        const float inv = 1.f / s;
        #pragma unroll
        for (int r = 0; r < TOPK; r++) {
            scores [(size_t)warp * TOPK + r] = e[r] * inv;
            indices[(size_t)warp * TOPK + r] = (float)topi[r];
        }
    }
}

// ---------------------------------------------------------------------------
extern "C" void kernel_launch(void* const* d_in, const int* in_sizes, int n_in,
                              void* d_out, int out_size)
{
    const float* hs = (const float*)d_in[0];   // hidden_states [T, 4096]
    const float* w  = (const float*)d_in[1];   // weight        [64, 4096]
    const int T = in_sizes[0] / H_DIM;

    float* out     = (float*)d_out;
    float* logits  = out;
    float* scores  = out + (size_t)T * E_DIM;
    float* indices = scores + (size_t)T * TOPK;

    cudaFuncSetAttribute(router_gemm_tc, cudaFuncAttributeMaxDynamicSharedMemorySize, DYN_SZ);
    router_gemm_tc<<<T / BM, THREADS, DYN_SZ>>>(hs, w, logits);

    const int warps_per_block = 256 / 32;
    const int grid = (T + warps_per_block - 1) / warps_per_block;
    topk_kernel<<<grid, 256>>>(logits, scores, indices, T);
}

// round 9
// speedup vs baseline: 2.4588x; 1.6930x over previous
#include <cuda_runtime.h>
#include <cuda_bf16.h>
#include <math.h>
#include <stdint.h>

#define H_DIM 4096
#define E_DIM 64
#define TOPK  8
#define BM    128                 // tokens per CTA
#define KC    64                  // K elements per chunk (= one accumulation segment)
#define NCHUNK (H_DIM / KC)       // 64
#define THREADS 512

#define A_PL  (BM * KC * 2)       // 16384 B per A bf16 plane
#define B_PL  (E_DIM * KC * 2)    // 8192  B per B bf16 plane
#define STAGE_SZ (3 * A_PL + 3 * B_PL)   // 73728 B
#define TILE_SZ (2 * STAGE_SZ)           // 147456 B
#define DYN_SZ (TILE_SZ + 256)

__device__ __forceinline__ uint32_t s2u(const void* p) {
    uint32_t a;
    asm("{ .reg .u64 t; cvta.to.shared.u64 t, %1; cvt.u32.u64 %0, t; }" : "=r"(a) : "l"(p));
    return a;
}
__device__ __forceinline__ uint32_t swz(uint32_t b) { return b ^ ((b >> 3) & 0x70); }

// 3-way bf16 split of one float4: v = h + m + l  (verified R5/R8)
__device__ __forceinline__ void cvt_store3(float4 v, uint32_t hB, uint32_t mB, uint32_t lB,
                                           int row, int c4) {
    uint32_t h01, h23, m01, m23, l01, l23;
    asm("cvt.rn.bf16x2.f32 %0, %1, %2;" : "=r"(h01) : "f"(v.y), "f"(v.x));
    asm("cvt.rn.bf16x2.f32 %0, %1, %2;" : "=r"(h23) : "f"(v.w), "f"(v.z));
    float h0 = __uint_as_float(h01 << 16);
    float h1 = __uint_as_float(h01 & 0xFFFF0000u);
    float h2 = __uint_as_float(h23 << 16);
    float h3 = __uint_as_float(h23 & 0xFFFF0000u);
    float r0 = v.x - h0, r1 = v.y - h1, r2 = v.z - h2, r3 = v.w - h3;
    asm("cvt.rn.bf16x2.f32 %0, %1, %2;" : "=r"(m01) : "f"(r1), "f"(r0));
    asm("cvt.rn.bf16x2.f32 %0, %1, %2;" : "=r"(m23) : "f"(r3), "f"(r2));
    float q0 = __uint_as_float(m01 << 16);
    float q1 = __uint_as_float(m01 & 0xFFFF0000u);
    float q2 = __uint_as_float(m23 << 16);
    float q3 = __uint_as_float(m23 & 0xFFFF0000u);
    asm("cvt.rn.bf16x2.f32 %0, %1, %2;" : "=r"(l01) : "f"(r1 - q1), "f"(r0 - q0));
    asm("cvt.rn.bf16x2.f32 %0, %1, %2;" : "=r"(l23) : "f"(r3 - q3), "f"(r2 - q2));
    uint32_t off = swz((uint32_t)(row * 128 + c4 * 8));
    asm volatile("st.shared.v2.b32 [%0], {%1,%2};" :: "r"(hB + off), "r"(h01), "r"(h23));
    asm volatile("st.shared.v2.b32 [%0], {%1,%2};" :: "r"(mB + off), "r"(m01), "r"(m23));
    asm volatile("st.shared.v2.b32 [%0], {%1,%2};" :: "r"(lB + off), "r"(l01), "r"(l23));
}

__device__ __forceinline__ void load_chunk(const float* __restrict__ A,
                                           const float* __restrict__ W,
                                           int m0, int chunk, int tid,
                                           float4* ra, float4* rb) {
    const int k0 = chunk * KC;
    #pragma unroll
    for (int i = 0; i < 4; i++) {                 // 4*512 = 2048 = 128 rows x 16
        int idx = tid + i * THREADS;
        int row = idx >> 4;
        int c4  = idx & 15;
        ra[i] = *reinterpret_cast<const float4*>(A + (size_t)(m0 + row) * H_DIM + k0 + c4 * 4);
    }
    #pragma unroll
    for (int i = 0; i < 2; i++) {                 // 2*512 = 1024 = 64 rows x 16
        int idx = tid + i * THREADS;
        int row = idx >> 4;
        int c4  = idx & 15;
        rb[i] = *reinterpret_cast<const float4*>(W + (size_t)row * H_DIM + k0 + c4 * 4);
    }
}

__device__ __forceinline__ void ldsm4(uint32_t addr, uint32_t& r0, uint32_t& r1,
                                      uint32_t& r2, uint32_t& r3) {
    asm volatile("ldmatrix.sync.aligned.m8n8.x4.shared.b16 {%0,%1,%2,%3}, [%4];"
                 : "=r"(r0), "=r"(r1), "=r"(r2), "=r"(r3) : "r"(addr));
}

__device__ __forceinline__ void mma16816(float* d, const uint32_t* a, const uint32_t* b) {
    asm volatile(
        "mma.sync.aligned.m16n8k16.row.col.f32.bf16.bf16.f32 "
        "{%0,%1,%2,%3}, {%4,%5,%6,%7}, {%8,%9}, {%0,%1,%2,%3};"
        : "+f"(d[0]), "+f"(d[1]), "+f"(d[2]), "+f"(d[3])
        : "r"(a[0]), "r"(a[1]), "r"(a[2]), "r"(a[3]), "r"(b[0]), "r"(b[1]));
}

// ---------------------------------------------------------------------------
// HMMA bf16 3-way-split GEMM, segmented accumulation (numerics == R8).
// 16 warps: warp = (row_group 0-7, expert_half 0-1); 16 rows x 32 experts
// per warp -> 16+16 accumulator regs per thread, ~100 total (no spills).
// ---------------------------------------------------------------------------
__global__ __launch_bounds__(THREADS, 1) void router_gemm_tc(
    const float* __restrict__ A, const float* __restrict__ W,
    float* __restrict__ logits)
{
    extern __shared__ char dsm[];
    const uint32_t base = (s2u(dsm) + 127u) & ~127u;
    uint32_t stage_base[2] = { base, base + STAGE_SZ };

    const int tid  = threadIdx.x;
    const int warp = tid >> 5;
    const int lane = tid & 31;
    const int m0   = blockIdx.x * BM;

    const int rg = warp >> 1;     // row group: rows rg*16 .. rg*16+15
    const int eh = warp & 1;      // expert half: experts eh*32 .. eh*32+31

    const int a_row   = rg * 16 + (lane & 15);
    const int a_khalf = lane >> 4;
    const uint32_t a_off0 = (uint32_t)(a_row * 128 + a_khalf * 16);
    const int b_rowl  = ((lane >> 4) << 3) + (lane & 7);
    const int b_khalf = (lane >> 3) & 1;
    // expert-half pairs: p = 2*eh, 2*eh+1  (each pair = 2 n-tiles of 8 experts)
    const uint32_t b_off0 = (uint32_t)(b_rowl * 128 + b_khalf * 16 + eh * 2 * 2048);

    float accM[4][4];
    #pragma unroll
    for (int nt = 0; nt < 4; nt++)
        #pragma unroll
        for (int j = 0; j < 4; j++) accM[nt][j] = 0.f;

    float4 na[4], nb[2];
    load_chunk(A, W, m0, 0, tid, na, nb);

    for (int chunk = 0; chunk < NCHUNK; ++chunk) {
        const int s = chunk & 1;
        const uint32_t aH  = stage_base[s];
        const uint32_t aM  = aH + A_PL;
        const uint32_t aL  = aM + A_PL;
        const uint32_t bH  = aL + A_PL;
        const uint32_t bMp = bH + B_PL;
        const uint32_t bLp = bMp + B_PL;

        // convert + store current registers, THEN refill them (register WAR is free)
        #pragma unroll
        for (int i = 0; i < 4; i++) {
            int idx = tid + i * THREADS;
            cvt_store3(na[i], aH, aM, aL, idx >> 4, idx & 15);
        }
        #pragma unroll
        for (int i = 0; i < 2; i++) {
            int idx = tid + i * THREADS;
            cvt_store3(nb[i], bH, bMp, bLp, idx >> 4, idx & 15);
        }
        if (chunk + 1 < NCHUNK) load_chunk(A, W, m0, chunk + 1, tid, na, nb);
        __syncthreads();

        float accS[4][4];
        #pragma unroll
        for (int nt = 0; nt < 4; nt++)
            #pragma unroll
            for (int j = 0; j < 4; j++) accS[nt][j] = 0.f;

        #pragma unroll
        for (int ks = 0; ks < 4; ks++) {
            const uint32_t ka = (uint32_t)(ks * 32);
            uint32_t ah[4], am[4], al[4];
            ldsm4(aH + swz(a_off0 + ka), ah[0], ah[1], ah[2], ah[3]);
            ldsm4(aM + swz(a_off0 + ka), am[0], am[1], am[2], am[3]);
            ldsm4(aL + swz(a_off0 + ka), al[0], al[1], al[2], al[3]);

            uint32_t bf[4][2];
            const uint32_t bo0 = swz(b_off0 + ka);
            const uint32_t bo1 = swz(b_off0 + 2048 + ka);

            // B-plane hi: terms hh, mh, lh
            ldsm4(bH + bo0, bf[0][0], bf[0][1], bf[1][0], bf[1][1]);
            ldsm4(bH + bo1, bf[2][0], bf[2][1], bf[3][0], bf[3][1]);
            #pragma unroll
            for (int nt = 0; nt < 4; nt++) mma16816(accS[nt], ah, bf[nt]);
            #pragma unroll
            for (int nt = 0; nt < 4; nt++) mma16816(accS[nt], am, bf[nt]);
            #pragma unroll
            for (int nt = 0; nt < 4; nt++) mma16816(accS[nt], al, bf[nt]);

            // B-plane mid: terms hm, mm
            ldsm4(bMp + bo0, bf[0][0], bf[0][1], bf[1][0], bf[1][1]);
            ldsm4(bMp + bo1, bf[2][0], bf[2][1], bf[3][0], bf[3][1]);
            #pragma unroll
            for (int nt = 0; nt < 4; nt++) mma16816(accS[nt], ah, bf[nt]);
            #pragma unroll
            for (int nt = 0; nt < 4; nt++) mma16816(accS[nt], am, bf[nt]);

            // B-plane lo: term hl
            ldsm4(bLp + bo0, bf[0][0], bf[0][1], bf[1][0], bf[1][1]);
            ldsm4(bLp + bo1, bf[2][0], bf[2][1], bf[3][0], bf[3][1]);
            #pragma unroll
            for (int nt = 0; nt < 4; nt++) mma16816(accS[nt], ah, bf[nt]);
        }

        #pragma unroll
        for (int nt = 0; nt < 4; nt++)
            #pragma unroll
            for (int j = 0; j < 4; j++) accM[nt][j] += accS[nt][j];
    }

    // epilogue: rows m0 + rg*16 + {lane>>2, +8}, experts eh*32 + nt*8 + 2*(lane&3)
    const int r0  = m0 + rg * 16 + (lane >> 2);
    const int col = eh * 32 + (lane & 3) * 2;
    #pragma unroll
    for (int nt = 0; nt < 4; nt++) {
        float* d0 = logits + (size_t)r0 * E_DIM + nt * 8 + col;
        float* d1 = logits + (size_t)(r0 + 8) * E_DIM + nt * 8 + col;
        *reinterpret_cast<float2*>(d0) = make_float2(accM[nt][0], accM[nt][1]);
        *reinterpret_cast<float2*>(d1) = make_float2(accM[nt][2], accM[nt][3]);
    }
}

// ---------------------------------------------------------------------------
// Kernel 2: top-8 + renormalized softmax scores (unchanged, verified)
// ---------------------------------------------------------------------------
__global__ __launch_bounds__(256) void topk_kernel(
    const float* __restrict__ logits,
    float* __restrict__ scores,
    float* __restrict__ indices, int T)
{
    const int warp = (int)((blockIdx.x * blockDim.x + threadIdx.x) >> 5);
    const int lane = threadIdx.x & 31;
    if (warp >= T) return;

    const float* lg = logits + (size_t)warp * E_DIM;
    float v0 = lg[lane];
    float v1 = lg[lane + 32];

    float topv[TOPK];
    int   topi[TOPK];

    #pragma unroll
    for (int r = 0; r < TOPK; r++) {
        bool p   = (v0 >= v1);
        float lv = p ? v0 : v1;
        int   li = p ? lane : lane + 32;
        #pragma unroll
        for (int off = 16; off > 0; off >>= 1) {
            float ov = __shfl_xor_sync(0xffffffffu, lv, off);
            int   oi = __shfl_xor_sync(0xffffffffu, li, off);
            if (ov > lv || (ov == lv && oi < li)) { lv = ov; li = oi; }
        }
        topv[r] = lv; topi[r] = li;
        if (li == lane)           v0 = -INFINITY;
        else if (li == lane + 32) v1 = -INFINITY;
    }

    if (lane == 0) {
        const float m = topv[0];
        float e[TOPK], s = 0.f;
        #pragma unroll
        for (int r = 0; r < TOPK; r++) { e[r] = expf(topv[r] - m); s += e[r]; }
        const float inv = 1.f / s;
        #pragma unroll
        for (int r = 0; r < TOPK; r++) {
            scores [(size_t)warp * TOPK + r] = e[r] * inv;
            indices[(size_t)warp * TOPK + r] = (float)topi[r];
        }
    }
}

// ---------------------------------------------------------------------------
extern "C" void kernel_launch(void* const* d_in, const int* in_sizes, int n_in,
                              void* d_out, int out_size)
{
    const float* hs = (const float*)d_in[0];   // hidden_states [T, 4096]
    const float* w  = (const float*)d_in[1];   // weight        [64, 4096]
    const int T = in_sizes[0] / H_DIM;

    float* out     = (float*)d_out;
    float* logits  = out;
    float* scores  = out + (size_t)T * E_DIM;
    float* indices = scores + (size_t)T * TOPK;

    cudaFuncSetAttribute(router_gemm_tc, cudaFuncAttributeMaxDynamicSharedMemorySize, DYN_SZ);
    router_gemm_tc<<<T / BM, THREADS, DYN_SZ>>>(hs, w, logits);

    const int warps_per_block = 256 / 32;
    const int grid = (T + warps_per_block - 1) / warps_per_block;
    topk_kernel<<<grid, 256>>>(logits, scores, indices, T);
}